// round 7
// baseline (speedup 1.0000x reference)
#include <cuda_runtime.h>
#include <cuda_bf16.h>
#include <math.h>
#include <stdint.h>

// Problem constants: B=4096, D_IN=512, H=512, E=256, V=512, L=32
#define Bb   4096
#define DIN  512
#define Hh   512
#define Ee   256
#define Vv   512
#define Ll   32
#define MIN_REAL_F (-3.4028234663852886e+38f)

// Persistent scratch (device globals; no allocations allowed)
__device__ float g_h[Bb * Hh];
__device__ float g_logits[Bb * Vv];

__device__ __nv_bfloat16 g_xb[Bb * DIN];
__device__ __nv_bfloat16 g_Wab[Hh * DIN];
__device__ __nv_bfloat16 g_Wihb[3 * Hh * Ee];
__device__ __nv_bfloat16 g_Whhb[3 * Hh * Hh];
__device__ __nv_bfloat16 g_Woutb[Vv * Hh];
__device__ __nv_bfloat16 g_Wembb[Ee * Vv];
__device__ __nv_bfloat16 g_hbA[Bb * Hh];
__device__ __nv_bfloat16 g_hbB[Bb * Hh];
__device__ __nv_bfloat16 g_eb[Bb * Ee];
__device__ __nv_bfloat16 g_sampb[Bb * Vv];

// ---------------------------------------------------------------------------
// PTX helpers
// ---------------------------------------------------------------------------
__device__ __forceinline__ uint32_t smem_u32(const void* p) {
    return (uint32_t)__cvta_generic_to_shared(p);
}
__device__ __forceinline__ void cp16(uint32_t s, const void* g) {
    asm volatile("cp.async.cg.shared.global [%0], [%1], 16;\n" :: "r"(s), "l"(g));
}
__device__ __forceinline__ void cp_commit() {
    asm volatile("cp.async.commit_group;\n");
}
template<int N> __device__ __forceinline__ void cp_wait() {
    asm volatile("cp.async.wait_group %0;\n" :: "n"(N));
}
__device__ __forceinline__ void ldsm4(uint32_t& r0, uint32_t& r1,
                                      uint32_t& r2, uint32_t& r3, uint32_t a) {
    asm volatile("ldmatrix.sync.aligned.m8n8.x4.shared.b16 {%0,%1,%2,%3}, [%4];\n"
                 : "=r"(r0), "=r"(r1), "=r"(r2), "=r"(r3) : "r"(a));
}
__device__ __forceinline__ void mma_bf16(float c[4], const uint32_t a[4],
                                         uint32_t b0, uint32_t b1) {
    asm volatile(
        "mma.sync.aligned.m16n8k16.row.col.f32.bf16.bf16.f32 "
        "{%0,%1,%2,%3}, {%4,%5,%6,%7}, {%8,%9}, {%0,%1,%2,%3};\n"
        : "+f"(c[0]), "+f"(c[1]), "+f"(c[2]), "+f"(c[3])
        : "r"(a[0]), "r"(a[1]), "r"(a[2]), "r"(a[3]), "r"(b0), "r"(b1));
}

// ---------------------------------------------------------------------------
// Generic bf16 HMMA GEMM (used for h0 / logits / emb):
// out[M,N] = A[M,K] @ W[N,K]^T + bias ; BK=64, 3-stage cp.async.
// ---------------------------------------------------------------------------
struct GemmArgs {
    const __nv_bfloat16* A;
    const __nv_bfloat16* W;
    const float* bias;
    float* C;                 // nullable fp32 out
    __nv_bfloat16* Cb;        // nullable bf16 out
    int lda;
    int ldc;
};

template<int BM, int BN, int WM, int WN>
__global__ __launch_bounds__(256) void tcb_gemm(GemmArgs a0, GemmArgs a1,
                                                int K0, int K1)
{
    constexpr int BK = 64;
    constexpr int STAGES = 3;
    constexpr int WARPS_M = BM / WM;
    constexpr int MI = WM / 16;
    constexpr int NJ = WN / 8;
    constexpr int NJ2 = WN / 16;
    constexpr int ACH = BM * 8 / 256;
    constexpr int WCH = BN * 8 / 256;
    constexpr int ABYTES = BM * 128;
    constexpr int WBYTES = BN * 128;

    extern __shared__ char dsm[];
    const GemmArgs ga = blockIdx.z ? a1 : a0;
    const int K = blockIdx.z ? K1 : K0;

    const uint32_t sbase = smem_u32(dsm);
    const uint32_t aBase = sbase;
    const uint32_t wBase = sbase + STAGES * ABYTES;

    const int tid  = threadIdx.x;
    const int warp = tid >> 5;
    const int lane = tid & 31;
    const int g = lane >> 2;
    const int t = lane & 3;
    const int wm = (warp % WARPS_M) * WM;
    const int wn = (warp / WARPS_M) * WN;
    const int bm = blockIdx.y * BM;
    const int bn = blockIdx.x * BN;
    const int lrow = lane & 15;
    const int lsel = lane >> 4;

    float acc[MI][NJ][4];
#pragma unroll
    for (int i = 0; i < MI; i++)
#pragma unroll
        for (int j = 0; j < NJ; j++)
#pragma unroll
            for (int r = 0; r < 4; r++) acc[i][j][r] = 0.0f;

    const int T = K / BK;

    auto load_stage = [&](int s, int k0) {
        const __nv_bfloat16* Ap = ga.A + (size_t)bm * ga.lda + k0;
        const __nv_bfloat16* Wp = ga.W + (size_t)bn * K + k0;
        const uint32_t as = aBase + s * ABYTES;
        const uint32_t ws = wBase + s * WBYTES;
#pragma unroll
        for (int i = 0; i < ACH; i++) {
            int cid = tid + i * 256;
            int r = cid >> 3, c = cid & 7;
            cp16(as + r * 128 + ((c ^ (r & 7)) << 4),
                 Ap + (size_t)r * ga.lda + c * 8);
        }
#pragma unroll
        for (int i = 0; i < WCH; i++) {
            int cid = tid + i * 256;
            int r = cid >> 3, c = cid & 7;
            cp16(ws + r * 128 + ((c ^ (r & 7)) << 4),
                 Wp + (size_t)r * K + c * 8);
        }
    };

    load_stage(0, 0);  cp_commit();
    if (T > 1) load_stage(1, BK);
    cp_commit();

    for (int kt = 0; kt < T; kt++) {
        const int s = kt % STAGES;
        cp_wait<1>();
        __syncthreads();
        const int pf = kt + 2;
        if (pf < T) load_stage(pf % STAGES, pf * BK);
        cp_commit();

        const uint32_t as = aBase + s * ABYTES;
        const uint32_t ws = wBase + s * WBYTES;
#pragma unroll
        for (int kh = 0; kh < BK / 16; kh++) {
            const int cch = kh * 2 + lsel;
            uint32_t af[MI][4];
#pragma unroll
            for (int i = 0; i < MI; i++) {
                int row = wm + i * 16 + lrow;
                ldsm4(af[i][0], af[i][1], af[i][2], af[i][3],
                      as + row * 128 + ((cch ^ (row & 7)) << 4));
            }
            uint32_t bfr[NJ2][4];
#pragma unroll
            for (int j = 0; j < NJ2; j++) {
                int row = wn + j * 16 + lrow;
                ldsm4(bfr[j][0], bfr[j][1], bfr[j][2], bfr[j][3],
                      ws + row * 128 + ((cch ^ (row & 7)) << 4));
            }
#pragma unroll
            for (int i = 0; i < MI; i++)
#pragma unroll
                for (int j = 0; j < NJ2; j++) {
                    mma_bf16(acc[i][2 * j],     af[i], bfr[j][0], bfr[j][2]);
                    mma_bf16(acc[i][2 * j + 1], af[i], bfr[j][1], bfr[j][3]);
                }
        }
        __syncthreads();
    }

#pragma unroll
    for (int j = 0; j < NJ; j++) {
        const int col = bn + wn + j * 8 + 2 * t;
        const float b0 = ga.bias[col];
        const float b1 = ga.bias[col + 1];
#pragma unroll
        for (int i = 0; i < MI; i++) {
            const int row = bm + wm + i * 16 + g;
            float v00 = acc[i][j][0] + b0, v01 = acc[i][j][1] + b1;
            float v10 = acc[i][j][2] + b0, v11 = acc[i][j][3] + b1;
            if (ga.C) {
                *(float2*)(ga.C + (size_t)row * ga.ldc + col)       = make_float2(v00, v01);
                *(float2*)(ga.C + (size_t)(row + 8) * ga.ldc + col) = make_float2(v10, v11);
            }
            if (ga.Cb) {
                *(__nv_bfloat162*)(ga.Cb + (size_t)row * ga.ldc + col) =
                    __floats2bfloat162_rn(v00, v01);
                *(__nv_bfloat162*)(ga.Cb + (size_t)(row + 8) * ga.ldc + col) =
                    __floats2bfloat162_rn(v10, v11);
            }
        }
    }
}

// ---------------------------------------------------------------------------
// Fused GRU cell: one CTA owns a 128x64 tile of h.
// Phase A: gh = hb_in @ W_hh^T (K=512) into 3 acc sets (r,z,n row-blocks).
// Spill gh_n to smem. Phase B: gi = eb @ W_ih^T (K=256) accumulated onto
// r/z sums + fresh gi_n. Epilogue: GRU gates, write h (fp32, in-place) and
// hb_out (bf16, double-buffered).
// ---------------------------------------------------------------------------
#define FG_ABYTES 16384                        // 128 rows * 128B
#define FG_WBYTES 24576                        // 192 rows * 128B
#define FG_STAGE  (FG_ABYTES + FG_WBYTES)      // 40960
#define FG_SPILL  (3 * FG_STAGE)               // 122880
#define FG_SMEM   (FG_SPILL + 128 * 68 * 4)    // 157696

__global__ __launch_bounds__(256, 1) void fused_gru_kernel(
    const __nv_bfloat16* __restrict__ hbin,
    const __nv_bfloat16* __restrict__ ebin,
    const __nv_bfloat16* __restrict__ Whh,
    const __nv_bfloat16* __restrict__ Wih,
    const float* __restrict__ b_ih, const float* __restrict__ b_hh,
    float* __restrict__ h, __nv_bfloat16* __restrict__ hbout)
{
    extern __shared__ char dsm[];
    const uint32_t sbase = smem_u32(dsm);
    float* spill = (float*)(dsm + FG_SPILL);

    const int tid  = threadIdx.x;
    const int warp = tid >> 5;
    const int lane = tid & 31;
    const int g = lane >> 2;
    const int t = lane & 3;
    const int lrow = lane & 15;
    const int lsel = lane >> 4;
    const int wm = (warp & 3) * 32;     // 4 warp-rows
    const int wn = (warp >> 2) * 32;    // 2 warp-cols
    const int bm = blockIdx.y * 128;
    const int c0 = blockIdx.x * 64;

    float acc[3][2][4][4];              // [gate][i][j][frag]
#pragma unroll
    for (int gset = 0; gset < 3; gset++)
#pragma unroll
        for (int i = 0; i < 2; i++)
#pragma unroll
            for (int j = 0; j < 4; j++)
#pragma unroll
                for (int r = 0; r < 4; r++) acc[gset][i][j][r] = 0.0f;

    // stage loader: A 128 rows (1024 chunks), W 3x64 rows (1536 chunks)
    auto load_stage = [&](int s, int k0, const __nv_bfloat16* A, int ldaA,
                          const __nv_bfloat16* W, int ldaW) {
        const uint32_t as = sbase + s * FG_STAGE;
        const uint32_t ws = as + FG_ABYTES;
#pragma unroll
        for (int i = 0; i < 4; i++) {
            int cid = tid + i * 256;
            int r = cid >> 3, c = cid & 7;
            cp16(as + r * 128 + ((c ^ (r & 7)) << 4),
                 A + (size_t)(bm + r) * ldaA + k0 + c * 8);
        }
#pragma unroll
        for (int i = 0; i < 6; i++) {
            int cid = tid + i * 256;
            int r = cid >> 3, c = cid & 7;
            int blk = r >> 6, wr = r & 63;
            cp16(ws + r * 128 + ((c ^ (r & 7)) << 4),
                 W + (size_t)(blk * Hh + c0 + wr) * ldaW + k0 + c * 8);
        }
    };

    auto compute_stage = [&](int s) {
        const uint32_t as = sbase + s * FG_STAGE;
        const uint32_t ws = as + FG_ABYTES;
#pragma unroll
        for (int kh = 0; kh < 4; kh++) {
            const int cch = kh * 2 + lsel;
            uint32_t af[2][4];
#pragma unroll
            for (int i = 0; i < 2; i++) {
                int row = wm + i * 16 + lrow;
                ldsm4(af[i][0], af[i][1], af[i][2], af[i][3],
                      as + row * 128 + ((cch ^ (row & 7)) << 4));
            }
#pragma unroll
            for (int b = 0; b < 3; b++) {
#pragma unroll
                for (int j2 = 0; j2 < 2; j2++) {
                    int row = b * 64 + wn + j2 * 16 + lrow;
                    uint32_t b0, b1, b2, b3;
                    ldsm4(b0, b1, b2, b3,
                          ws + row * 128 + ((cch ^ (row & 7)) << 4));
#pragma unroll
                    for (int i = 0; i < 2; i++) {
                        mma_bf16(acc[b][i][2 * j2],     af[i], b0, b2);
                        mma_bf16(acc[b][i][2 * j2 + 1], af[i], b1, b3);
                    }
                }
            }
        }
    };

    // ---- Phase A: gh (K = 512, 8 chunks) ----
    load_stage(0, 0,  hbin, Hh, Whh, Hh); cp_commit();
    load_stage(1, 64, hbin, Hh, Whh, Hh); cp_commit();
    for (int tt = 0; tt < 8; tt++) {
        cp_wait<1>();
        __syncthreads();
        const int pf = tt + 2;
        if (pf < 8) load_stage(pf % 3, pf * 64, hbin, Hh, Whh, Hh);
        cp_commit();
        compute_stage(tt % 3);
    }
    __syncthreads();   // all ldsm done before phase B overwrites stages

    // spill gh_n, reset acc[2] for gi_n
#pragma unroll
    for (int i = 0; i < 2; i++)
#pragma unroll
        for (int j = 0; j < 4; j++) {
            const int rowL = wm + i * 16 + g;
            const int colL = wn + j * 8 + 2 * t;
            *(float2*)&spill[rowL * 68 + colL] =
                make_float2(acc[2][i][j][0], acc[2][i][j][1]);
            *(float2*)&spill[(rowL + 8) * 68 + colL] =
                make_float2(acc[2][i][j][2], acc[2][i][j][3]);
#pragma unroll
            for (int r = 0; r < 4; r++) acc[2][i][j][r] = 0.0f;
        }

    // ---- Phase B: gi (K = 256, 4 chunks) ----
    load_stage(0, 0,  ebin, Ee, Wih, Ee); cp_commit();
    load_stage(1, 64, ebin, Ee, Wih, Ee); cp_commit();
    for (int tt = 0; tt < 4; tt++) {
        cp_wait<1>();
        __syncthreads();
        const int pf = tt + 2;
        if (pf < 4) load_stage(pf % 3, pf * 64, ebin, Ee, Wih, Ee);
        cp_commit();
        compute_stage(tt % 3);
    }

    // ---- Epilogue: GRU gates ----
#pragma unroll
    for (int j = 0; j < 4; j++) {
        const int colL = wn + j * 8 + 2 * t;
        const int colG = c0 + colL;
        float2 bir = *(const float2*)(b_ih + colG);
        float2 bhr = *(const float2*)(b_hh + colG);
        float2 biz = *(const float2*)(b_ih + Hh + colG);
        float2 bhz = *(const float2*)(b_hh + Hh + colG);
        float2 bin = *(const float2*)(b_ih + 2 * Hh + colG);
        float2 bhn = *(const float2*)(b_hh + 2 * Hh + colG);
        const float br0 = bir.x + bhr.x, br1 = bir.y + bhr.y;
        const float bz0 = biz.x + bhz.x, bz1 = biz.y + bhz.y;
#pragma unroll
        for (int i = 0; i < 2; i++) {
            const int rowL = wm + i * 16 + g;
#pragma unroll
            for (int rv = 0; rv < 2; rv++) {
                const int row = rowL + rv * 8;
                const int rb = rv * 2;
                float rs0 = acc[0][i][j][rb]     + br0;
                float rs1 = acc[0][i][j][rb + 1] + br1;
                float zs0 = acc[1][i][j][rb]     + bz0;
                float zs1 = acc[1][i][j][rb + 1] + bz1;
                float gin0 = acc[2][i][j][rb]     + bin.x;
                float gin1 = acc[2][i][j][rb + 1] + bin.y;
                float2 ghn = *(float2*)&spill[row * 68 + colL];
                float ghn0 = ghn.x + bhn.x;
                float ghn1 = ghn.y + bhn.y;

                float r0 = 1.0f / (1.0f + expf(-rs0));
                float r1 = 1.0f / (1.0f + expf(-rs1));
                float z0 = 1.0f / (1.0f + expf(-zs0));
                float z1 = 1.0f / (1.0f + expf(-zs1));
                float n0 = tanhf(gin0 + r0 * ghn0);
                float n1 = tanhf(gin1 + r1 * ghn1);

                float* hp = h + (size_t)(bm + row) * Hh + colG;
                float2 hold = *(float2*)hp;
                float h0v = (1.0f - z0) * n0 + z0 * hold.x;
                float h1v = (1.0f - z1) * n1 + z1 * hold.y;
                *(float2*)hp = make_float2(h0v, h1v);
                *(__nv_bfloat162*)(hbout + (size_t)(bm + row) * Hh + colG) =
                    __floats2bfloat162_rn(h0v, h1v);
            }
        }
    }
}

// ---------------------------------------------------------------------------
// fp32 -> bf16 conversion
// ---------------------------------------------------------------------------
__global__ void f2b_kernel(const float* __restrict__ in,
                           __nv_bfloat16* __restrict__ out, int n4)
{
    int i = blockIdx.x * blockDim.x + threadIdx.x;
    if (i < n4) {
        float4 v = ((const float4*)in)[i];
        ((__nv_bfloat162*)out)[2 * i]     = __floats2bfloat162_rn(v.x, v.y);
        ((__nv_bfloat162*)out)[2 * i + 1] = __floats2bfloat162_rn(v.z, v.w);
    }
}

__global__ void init_e_kernel(__nv_bfloat16* __restrict__ eb,
                              const float* __restrict__ sos)
{
    int idx = blockIdx.x * blockDim.x + threadIdx.x;
    if (idx < Bb * Ee) eb[idx] = __float2bfloat16(sos[idx & (Ee - 1)]);
}

// ---------------------------------------------------------------------------
// Gumbel-softmax + entropy, one WARP per row (V=512 -> 16 elems/lane)
// ---------------------------------------------------------------------------
__global__ __launch_bounds__(256) void gumbel_softmax_kernel(
    const float* __restrict__ logits,
    const float* __restrict__ noise,
    float* __restrict__ seq,
    __nv_bfloat16* __restrict__ sampb,
    float* __restrict__ ent)
{
    const int warp = threadIdx.x >> 5;
    const int lane = threadIdx.x & 31;
    const int b = blockIdx.x * 8 + warp;

    const float4* lg4 = (const float4*)(logits + (size_t)b * Vv);
    const float4* nz4 = (const float4*)(noise + (size_t)b * Vv);

    float tv[16];
    float m = -INFINITY;
#pragma unroll
    for (int i = 0; i < 4; i++) {
        float4 lv = lg4[i * 32 + lane];
        float4 uv = nz4[i * 32 + lane];
        tv[4 * i + 0] = lv.x - logf(-logf(uv.x));
        tv[4 * i + 1] = lv.y - logf(-logf(uv.y));
        tv[4 * i + 2] = lv.z - logf(-logf(uv.z));
        tv[4 * i + 3] = lv.w - logf(-logf(uv.w));
        m = fmaxf(m, fmaxf(fmaxf(tv[4 * i], tv[4 * i + 1]),
                           fmaxf(tv[4 * i + 2], tv[4 * i + 3])));
    }
#pragma unroll
    for (int o = 16; o; o >>= 1) m = fmaxf(m, __shfl_xor_sync(0xffffffffu, m, o));

    float s = 0.0f;
#pragma unroll
    for (int i = 0; i < 16; i++) { tv[i] = expf(tv[i] - m); s += tv[i]; }
#pragma unroll
    for (int o = 16; o; o >>= 1) s += __shfl_xor_sync(0xffffffffu, s, o);
    const float inv = 1.0f / s;

    float4* sq4 = (float4*)(seq + (size_t)b * (Ll * Vv));
    __nv_bfloat162* sb2 = (__nv_bfloat162*)(sampb + (size_t)b * Vv);
    float el = 0.0f;
#pragma unroll
    for (int i = 0; i < 4; i++) {
        float p0 = tv[4 * i] * inv,     p1 = tv[4 * i + 1] * inv;
        float p2 = tv[4 * i + 2] * inv, p3 = tv[4 * i + 3] * inv;
        sq4[i * 32 + lane] = make_float4(p0, p1, p2, p3);
        sb2[2 * (i * 32 + lane)]     = __floats2bfloat162_rn(p0, p1);
        sb2[2 * (i * 32 + lane) + 1] = __floats2bfloat162_rn(p2, p3);
        el += p0 * fmaxf(log2f(p0), MIN_REAL_F) + p1 * fmaxf(log2f(p1), MIN_REAL_F)
            + p2 * fmaxf(log2f(p2), MIN_REAL_F) + p3 * fmaxf(log2f(p3), MIN_REAL_F);
    }
#pragma unroll
    for (int o = 16; o; o >>= 1) el += __shfl_xor_sync(0xffffffffu, el, o);
    if (lane == 0) ent[(size_t)b * Ll] = -el;
}

// ---------------------------------------------------------------------------
// Host launcher
// ---------------------------------------------------------------------------
#define SMEM_HALF ((3 * (64 + 128) * 128))    // 73728

extern "C" void kernel_launch(void* const* d_in, const int* in_sizes, int n_in,
                              void* d_out, int out_size)
{
    const float* x       = (const float*)d_in[0];
    const float* noise   = (const float*)d_in[1];
    const float* b_agent = (const float*)d_in[3];
    const float* b_ih    = (const float*)d_in[6];
    const float* b_hh    = (const float*)d_in[7];
    const float* b_out   = (const float*)d_in[9];
    const float* b_emb   = (const float*)d_in[11];
    const float* sos     = (const float*)d_in[12];

    float* out = (float*)d_out;
    float* seq = out;                              // [B,L,V]
    float* ent = out + (size_t)Bb * Ll * Vv;       // [B,L]

    float *h, *logits;
    __nv_bfloat16 *xb, *Wab, *Wihb, *Whhb, *Woutb, *Wembb;
    __nv_bfloat16 *hbA, *hbB, *eb, *sampb;
    cudaGetSymbolAddress((void**)&h,      g_h);
    cudaGetSymbolAddress((void**)&logits, g_logits);
    cudaGetSymbolAddress((void**)&xb,     g_xb);
    cudaGetSymbolAddress((void**)&Wab,    g_Wab);
    cudaGetSymbolAddress((void**)&Wihb,   g_Wihb);
    cudaGetSymbolAddress((void**)&Whhb,   g_Whhb);
    cudaGetSymbolAddress((void**)&Woutb,  g_Woutb);
    cudaGetSymbolAddress((void**)&Wembb,  g_Wembb);
    cudaGetSymbolAddress((void**)&hbA,    g_hbA);
    cudaGetSymbolAddress((void**)&hbB,    g_hbB);
    cudaGetSymbolAddress((void**)&eb,     g_eb);
    cudaGetSymbolAddress((void**)&sampb,  g_sampb);

    cudaFuncSetAttribute((const void*)tcb_gemm<64, 128, 32, 32>,
                         cudaFuncAttributeMaxDynamicSharedMemorySize, SMEM_HALF);
    cudaFuncSetAttribute((const void*)fused_gru_kernel,
                         cudaFuncAttributeMaxDynamicSharedMemorySize, FG_SMEM);

    auto conv = [&](const void* src, __nv_bfloat16* dst, int n) {
        f2b_kernel<<<(n / 4 + 255) / 256, 256>>>((const float*)src, dst, n / 4);
    };
    conv(x,        xb,    Bb * DIN);
    conv(d_in[2],  Wab,   Hh * DIN);
    conv(d_in[4],  Wihb,  3 * Hh * Ee);
    conv(d_in[5],  Whhb,  3 * Hh * Hh);
    conv(d_in[8],  Woutb, Vv * Hh);
    conv(d_in[10], Wembb, Ee * Vv);
    init_e_kernel<<<(Bb * Ee + 255) / 256, 256>>>(eb, sos);

    GemmArgs Z = {};

    // h0 = x @ W_agent^T + b_agent  -> h fp32 + hbA bf16
    {
        GemmArgs a = {xb, Wab, b_agent, h, hbA, DIN, Hh};
        tcb_gemm<64, 128, 32, 32><<<dim3(Hh / 128, Bb / 64, 1), 256, SMEM_HALF>>>(
            a, Z, DIN, DIN);
    }

    for (int l = 0; l < Ll; l++) {
        __nv_bfloat16* hin  = (l & 1) ? hbB : hbA;
        __nv_bfloat16* hout = (l & 1) ? hbA : hbB;
        // fused GRU cell: gh + gi GEMMs + gates
        fused_gru_kernel<<<dim3(Hh / 64, Bb / 128), 256, FG_SMEM>>>(
            hin, eb, Whhb, Wihb, b_ih, b_hh, h, hout);
        // logits = h @ W_out^T + b_out
        GemmArgs alo = {hout, Woutb, b_out, logits, nullptr, Hh, Vv};
        tcb_gemm<64, 128, 32, 32><<<dim3(Vv / 128, Bb / 64, 1), 256, SMEM_HALF>>>(
            alo, Z, Hh, Hh);
        // sample + entropy
        gumbel_softmax_kernel<<<Bb / 8, 256>>>(logits,
                                               noise + (size_t)l * Bb * Vv,
                                               seq + (size_t)l * Vv, sampb,
                                               ent + l);
        // e = sample @ W_emb^T + b_emb
        GemmArgs aem = {sampb, Wembb, b_emb, nullptr, eb, Vv, Ee};
        tcb_gemm<64, 128, 32, 32><<<dim3(Ee / 128, Bb / 64, 1), 256, SMEM_HALF>>>(
            aem, Z, Vv, Vv);
    }
    (void)in_sizes; (void)n_in; (void)out_size;
}

// round 9
// speedup vs baseline: 1.0276x; 1.0276x over previous
#include <cuda_runtime.h>
#include <cuda_bf16.h>
#include <math.h>
#include <stdint.h>

// Problem constants: B=4096, D_IN=512, H=512, E=256, V=512, L=32
#define Bb   4096
#define DIN  512
#define Hh   512
#define Ee   256
#define Vv   512
#define Ll   32
#define MIN_REAL_F (-3.4028234663852886e+38f)

// Persistent scratch (device globals; no allocations allowed)
__device__ float g_h[Bb * Hh];
__device__ float g_logits[Bb * Vv];

__device__ __nv_bfloat16 g_xb[Bb * DIN];
__device__ __nv_bfloat16 g_Wab[Hh * DIN];
__device__ __nv_bfloat16 g_Wihb[3 * Hh * Ee];
__device__ __nv_bfloat16 g_Whhb[3 * Hh * Hh];
__device__ __nv_bfloat16 g_Woutb[Vv * Hh];
__device__ __nv_bfloat16 g_Wembb[Ee * Vv];
__device__ __nv_bfloat16 g_hb[Bb * Hh];
__device__ __nv_bfloat16 g_eb[Bb * Ee];
__device__ __nv_bfloat16 g_gib[Bb * 3 * Hh];
__device__ __nv_bfloat16 g_ghb[Bb * 3 * Hh];
__device__ __nv_bfloat16 g_sampb[Bb * Vv];

// ---------------------------------------------------------------------------
// PTX helpers
// ---------------------------------------------------------------------------
__device__ __forceinline__ uint32_t smem_u32(const void* p) {
    return (uint32_t)__cvta_generic_to_shared(p);
}
__device__ __forceinline__ void cp16(uint32_t s, const void* g) {
    asm volatile("cp.async.cg.shared.global [%0], [%1], 16;\n" :: "r"(s), "l"(g));
}
__device__ __forceinline__ void cp_commit() {
    asm volatile("cp.async.commit_group;\n");
}
template<int N> __device__ __forceinline__ void cp_wait() {
    asm volatile("cp.async.wait_group %0;\n" :: "n"(N));
}
__device__ __forceinline__ void ldsm4(uint32_t& r0, uint32_t& r1,
                                      uint32_t& r2, uint32_t& r3, uint32_t a) {
    asm volatile("ldmatrix.sync.aligned.m8n8.x4.shared.b16 {%0,%1,%2,%3}, [%4];\n"
                 : "=r"(r0), "=r"(r1), "=r"(r2), "=r"(r3) : "r"(a));
}
__device__ __forceinline__ void mma_bf16(float c[4], const uint32_t a[4],
                                         uint32_t b0, uint32_t b1) {
    asm volatile(
        "mma.sync.aligned.m16n8k16.row.col.f32.bf16.bf16.f32 "
        "{%0,%1,%2,%3}, {%4,%5,%6,%7}, {%8,%9}, {%0,%1,%2,%3};\n"
        : "+f"(c[0]), "+f"(c[1]), "+f"(c[2]), "+f"(c[3])
        : "r"(a[0]), "r"(a[1]), "r"(a[2]), "r"(a[3]), "r"(b0), "r"(b1));
}

// ---------------------------------------------------------------------------
// bf16 HMMA GEMM:  out[M,N] = A[M,K] @ W[N,K]^T + bias
// BK=64 (128B rows), 3-stage cp.async, swizzle chunk c^(r&7).
// One __syncthreads per k-chunk (top-of-loop sync also guards stage reuse).
// grid.z selects between two argument sets (fused independent GEMMs).
// ---------------------------------------------------------------------------
struct GemmArgs {
    const __nv_bfloat16* A;
    const __nv_bfloat16* W;
    const float* bias;
    float* C;                 // nullable fp32 out
    __nv_bfloat16* Cb;        // nullable bf16 out
    int lda;
    int ldc;
};

template<int BM, int BN, int WM, int WN>
__global__ __launch_bounds__(256) void tcb_gemm(GemmArgs a0, GemmArgs a1,
                                                int K0, int K1)
{
    constexpr int BK = 64;
    constexpr int STAGES = 3;
    constexpr int WARPS_M = BM / WM;
    constexpr int MI = WM / 16;
    constexpr int NJ = WN / 8;
    constexpr int NJ2 = WN / 16;
    constexpr int ACH = BM * 8 / 256;
    constexpr int WCH = BN * 8 / 256;
    constexpr int ABYTES = BM * 128;
    constexpr int WBYTES = BN * 128;

    extern __shared__ char dsm[];
    const GemmArgs ga = blockIdx.z ? a1 : a0;
    const int K = blockIdx.z ? K1 : K0;

    const uint32_t sbase = smem_u32(dsm);
    const uint32_t aBase = sbase;
    const uint32_t wBase = sbase + STAGES * ABYTES;

    const int tid  = threadIdx.x;
    const int warp = tid >> 5;
    const int lane = tid & 31;
    const int g = lane >> 2;
    const int t = lane & 3;
    const int wm = (warp % WARPS_M) * WM;
    const int wn = (warp / WARPS_M) * WN;
    const int bm = blockIdx.y * BM;
    const int bn = blockIdx.x * BN;
    const int lrow = lane & 15;
    const int lsel = lane >> 4;

    float acc[MI][NJ][4];
#pragma unroll
    for (int i = 0; i < MI; i++)
#pragma unroll
        for (int j = 0; j < NJ; j++)
#pragma unroll
            for (int r = 0; r < 4; r++) acc[i][j][r] = 0.0f;

    const int T = K / BK;

    auto load_stage = [&](int s, int k0) {
        const __nv_bfloat16* Ap = ga.A + (size_t)bm * ga.lda + k0;
        const __nv_bfloat16* Wp = ga.W + (size_t)bn * K + k0;
        const uint32_t as = aBase + s * ABYTES;
        const uint32_t ws = wBase + s * WBYTES;
#pragma unroll
        for (int i = 0; i < ACH; i++) {
            int cid = tid + i * 256;
            int r = cid >> 3, c = cid & 7;
            cp16(as + r * 128 + ((c ^ (r & 7)) << 4),
                 Ap + (size_t)r * ga.lda + c * 8);
        }
#pragma unroll
        for (int i = 0; i < WCH; i++) {
            int cid = tid + i * 256;
            int r = cid >> 3, c = cid & 7;
            cp16(ws + r * 128 + ((c ^ (r & 7)) << 4),
                 Wp + (size_t)r * K + c * 8);
        }
    };

    load_stage(0, 0);  cp_commit();
    if (T > 1) load_stage(1, BK);
    cp_commit();

    for (int kt = 0; kt < T; kt++) {
        const int s = kt % STAGES;
        cp_wait<1>();
        __syncthreads();            // stage s ready; also guards reuse of s
        const int pf = kt + 2;
        if (pf < T) load_stage(pf % STAGES, pf * BK);
        cp_commit();

        const uint32_t as = aBase + s * ABYTES;
        const uint32_t ws = wBase + s * WBYTES;
#pragma unroll
        for (int kh = 0; kh < BK / 16; kh++) {
            const int cch = kh * 2 + lsel;
            uint32_t af[MI][4];
#pragma unroll
            for (int i = 0; i < MI; i++) {
                int row = wm + i * 16 + lrow;
                ldsm4(af[i][0], af[i][1], af[i][2], af[i][3],
                      as + row * 128 + ((cch ^ (row & 7)) << 4));
            }
            uint32_t bfr[NJ2][4];
#pragma unroll
            for (int j = 0; j < NJ2; j++) {
                int row = wn + j * 16 + lrow;
                ldsm4(bfr[j][0], bfr[j][1], bfr[j][2], bfr[j][3],
                      ws + row * 128 + ((cch ^ (row & 7)) << 4));
            }
#pragma unroll
            for (int i = 0; i < MI; i++)
#pragma unroll
                for (int j = 0; j < NJ2; j++) {
                    mma_bf16(acc[i][2 * j],     af[i], bfr[j][0], bfr[j][2]);
                    mma_bf16(acc[i][2 * j + 1], af[i], bfr[j][1], bfr[j][3]);
                }
        }
        // no trailing sync: next iteration's top sync provides the ordering
    }

#pragma unroll
    for (int j = 0; j < NJ; j++) {
        const int col = bn + wn + j * 8 + 2 * t;
        const float b0 = ga.bias[col];
        const float b1 = ga.bias[col + 1];
#pragma unroll
        for (int i = 0; i < MI; i++) {
            const int row = bm + wm + i * 16 + g;
            float v00 = acc[i][j][0] + b0, v01 = acc[i][j][1] + b1;
            float v10 = acc[i][j][2] + b0, v11 = acc[i][j][3] + b1;
            if (ga.C) {
                *(float2*)(ga.C + (size_t)row * ga.ldc + col)       = make_float2(v00, v01);
                *(float2*)(ga.C + (size_t)(row + 8) * ga.ldc + col) = make_float2(v10, v11);
            }
            if (ga.Cb) {
                *(__nv_bfloat162*)(ga.Cb + (size_t)row * ga.ldc + col) =
                    __floats2bfloat162_rn(v00, v01);
                *(__nv_bfloat162*)(ga.Cb + (size_t)(row + 8) * ga.ldc + col) =
                    __floats2bfloat162_rn(v10, v11);
            }
        }
    }
}

// ---------------------------------------------------------------------------
// Fused fp32->bf16 conversion of all weights/inputs in ONE kernel.
// Segment table in float4 units (hardcoded sizes).
// ---------------------------------------------------------------------------
#define F4_X    (Bb * DIN / 4)            // 524288
#define F4_WA   (Hh * DIN / 4)            // 65536
#define F4_WIH  (3 * Hh * Ee / 4)         // 98304
#define F4_WHH  (3 * Hh * Hh / 4)         // 196608
#define F4_WOUT (Vv * Hh / 4)             // 65536
#define F4_WEMB (Ee * Vv / 4)             // 32768
#define F4_TOTAL (F4_X + F4_WA + F4_WIH + F4_WHH + F4_WOUT + F4_WEMB)

__global__ void conv_all_kernel(
    const float* __restrict__ x,     const float* __restrict__ Wa,
    const float* __restrict__ Wih,   const float* __restrict__ Whh,
    const float* __restrict__ Wout,  const float* __restrict__ Wemb,
    __nv_bfloat16* __restrict__ xb,   __nv_bfloat16* __restrict__ Wab,
    __nv_bfloat16* __restrict__ Wihb, __nv_bfloat16* __restrict__ Whhb,
    __nv_bfloat16* __restrict__ Woutb, __nv_bfloat16* __restrict__ Wembb)
{
    int i = blockIdx.x * blockDim.x + threadIdx.x;
    if (i >= F4_TOTAL) return;
    const float* src; __nv_bfloat16* dst; int off = i;
    if (off < F4_X) { src = x; dst = xb; }
    else if ((off -= F4_X) < F4_WA) { src = Wa; dst = Wab; }
    else if ((off -= F4_WA) < F4_WIH) { src = Wih; dst = Wihb; }
    else if ((off -= F4_WIH) < F4_WHH) { src = Whh; dst = Whhb; }
    else if ((off -= F4_WHH) < F4_WOUT) { src = Wout; dst = Woutb; }
    else { off -= F4_WOUT; src = Wemb; dst = Wembb; }
    float4 v = ((const float4*)src)[off];
    ((__nv_bfloat162*)dst)[2 * off]     = __floats2bfloat162_rn(v.x, v.y);
    ((__nv_bfloat162*)dst)[2 * off + 1] = __floats2bfloat162_rn(v.z, v.w);
}

__global__ void init_e_kernel(__nv_bfloat16* __restrict__ eb,
                              const float* __restrict__ sos)
{
    int idx = blockIdx.x * blockDim.x + threadIdx.x;
    if (idx < Bb * Ee) eb[idx] = __float2bfloat16(sos[idx & (Ee - 1)]);
}

// ---------------------------------------------------------------------------
// GRU gates (bf16 gi/gh, fp32 h state, dual h/hb write)
// ---------------------------------------------------------------------------
__global__ void gru_gates_kernel(const __nv_bfloat16* __restrict__ gi,
                                 const __nv_bfloat16* __restrict__ gh,
                                 float* __restrict__ h,
                                 __nv_bfloat16* __restrict__ hb)
{
    int idx = blockIdx.x * blockDim.x + threadIdx.x;
    if (idx >= Bb * Hh / 2) return;
    int b  = idx / (Hh / 2);
    int j2 = (idx - b * (Hh / 2)) * 2;

    const __nv_bfloat162* gi2 = (const __nv_bfloat162*)(gi + (size_t)b * 3 * Hh);
    const __nv_bfloat162* gh2 = (const __nv_bfloat162*)(gh + (size_t)b * 3 * Hh);
    float2 ir  = __bfloat1622float2(gi2[j2 >> 1]);
    float2 iz  = __bfloat1622float2(gi2[(Hh + j2) >> 1]);
    float2 inn = __bfloat1622float2(gi2[(2 * Hh + j2) >> 1]);
    float2 hr  = __bfloat1622float2(gh2[j2 >> 1]);
    float2 hz  = __bfloat1622float2(gh2[(Hh + j2) >> 1]);
    float2 hn  = __bfloat1622float2(gh2[(2 * Hh + j2) >> 1]);
    float2 hv  = *(float2*)(h + (size_t)b * Hh + j2);

    float2 o;
    {
        float r = 1.0f / (1.0f + expf(-(ir.x + hr.x)));
        float z = 1.0f / (1.0f + expf(-(iz.x + hz.x)));
        float n = tanhf(inn.x + r * hn.x);
        o.x = (1.0f - z) * n + z * hv.x;
    }
    {
        float r = 1.0f / (1.0f + expf(-(ir.y + hr.y)));
        float z = 1.0f / (1.0f + expf(-(iz.y + hz.y)));
        float n = tanhf(inn.y + r * hn.y);
        o.y = (1.0f - z) * n + z * hv.y;
    }
    *(float2*)(h + (size_t)b * Hh + j2) = o;
    *(__nv_bfloat162*)(hb + (size_t)b * Hh + j2) = __floats2bfloat162_rn(o.x, o.y);
}

// ---------------------------------------------------------------------------
// Gumbel-softmax + entropy, one WARP per row (V=512 -> 16 elems/lane)
// ---------------------------------------------------------------------------
__global__ __launch_bounds__(256) void gumbel_softmax_kernel(
    const float* __restrict__ logits,
    const float* __restrict__ noise,
    float* __restrict__ seq,
    __nv_bfloat16* __restrict__ sampb,
    float* __restrict__ ent)
{
    const int warp = threadIdx.x >> 5;
    const int lane = threadIdx.x & 31;
    const int b = blockIdx.x * 8 + warp;

    const float4* lg4 = (const float4*)(logits + (size_t)b * Vv);
    const float4* nz4 = (const float4*)(noise + (size_t)b * Vv);

    float tv[16];
    float m = -INFINITY;
#pragma unroll
    for (int i = 0; i < 4; i++) {
        float4 lv = lg4[i * 32 + lane];
        float4 uv = nz4[i * 32 + lane];
        tv[4 * i + 0] = lv.x - logf(-logf(uv.x));
        tv[4 * i + 1] = lv.y - logf(-logf(uv.y));
        tv[4 * i + 2] = lv.z - logf(-logf(uv.z));
        tv[4 * i + 3] = lv.w - logf(-logf(uv.w));
        m = fmaxf(m, fmaxf(fmaxf(tv[4 * i], tv[4 * i + 1]),
                           fmaxf(tv[4 * i + 2], tv[4 * i + 3])));
    }
#pragma unroll
    for (int o = 16; o; o >>= 1) m = fmaxf(m, __shfl_xor_sync(0xffffffffu, m, o));

    float s = 0.0f;
#pragma unroll
    for (int i = 0; i < 16; i++) { tv[i] = expf(tv[i] - m); s += tv[i]; }
#pragma unroll
    for (int o = 16; o; o >>= 1) s += __shfl_xor_sync(0xffffffffu, s, o);
    const float inv = 1.0f / s;

    float4* sq4 = (float4*)(seq + (size_t)b * (Ll * Vv));
    __nv_bfloat162* sb2 = (__nv_bfloat162*)(sampb + (size_t)b * Vv);
    float el = 0.0f;
#pragma unroll
    for (int i = 0; i < 4; i++) {
        float p0 = tv[4 * i] * inv,     p1 = tv[4 * i + 1] * inv;
        float p2 = tv[4 * i + 2] * inv, p3 = tv[4 * i + 3] * inv;
        sq4[i * 32 + lane] = make_float4(p0, p1, p2, p3);
        sb2[2 * (i * 32 + lane)]     = __floats2bfloat162_rn(p0, p1);
        sb2[2 * (i * 32 + lane) + 1] = __floats2bfloat162_rn(p2, p3);
        el += p0 * fmaxf(log2f(p0), MIN_REAL_F) + p1 * fmaxf(log2f(p1), MIN_REAL_F)
            + p2 * fmaxf(log2f(p2), MIN_REAL_F) + p3 * fmaxf(log2f(p3), MIN_REAL_F);
    }
#pragma unroll
    for (int o = 16; o; o >>= 1) el += __shfl_xor_sync(0xffffffffu, el, o);
    if (lane == 0) ent[(size_t)b * Ll] = -el;
}

// ---------------------------------------------------------------------------
// Host launcher (single stream)
// ---------------------------------------------------------------------------
#define SMEM_BIG  ((3 * (128 + 128) * 128))   // 98304
#define SMEM_HALF ((3 * (64 + 128) * 128))    // 73728

extern "C" void kernel_launch(void* const* d_in, const int* in_sizes, int n_in,
                              void* d_out, int out_size)
{
    const float* x       = (const float*)d_in[0];
    const float* noise   = (const float*)d_in[1];
    const float* b_agent = (const float*)d_in[3];
    const float* b_ih    = (const float*)d_in[6];
    const float* b_hh    = (const float*)d_in[7];
    const float* b_out   = (const float*)d_in[9];
    const float* b_emb   = (const float*)d_in[11];
    const float* sos     = (const float*)d_in[12];

    float* out = (float*)d_out;
    float* seq = out;                              // [B,L,V]
    float* ent = out + (size_t)Bb * Ll * Vv;       // [B,L]

    float *h, *logits;
    __nv_bfloat16 *xb, *Wab, *Wihb, *Whhb, *Woutb, *Wembb;
    __nv_bfloat16 *hb, *eb, *gib, *ghb, *sampb;
    cudaGetSymbolAddress((void**)&h,      g_h);
    cudaGetSymbolAddress((void**)&logits, g_logits);
    cudaGetSymbolAddress((void**)&xb,     g_xb);
    cudaGetSymbolAddress((void**)&Wab,    g_Wab);
    cudaGetSymbolAddress((void**)&Wihb,   g_Wihb);
    cudaGetSymbolAddress((void**)&Whhb,   g_Whhb);
    cudaGetSymbolAddress((void**)&Woutb,  g_Woutb);
    cudaGetSymbolAddress((void**)&Wembb,  g_Wembb);
    cudaGetSymbolAddress((void**)&hb,     g_hb);
    cudaGetSymbolAddress((void**)&eb,     g_eb);
    cudaGetSymbolAddress((void**)&gib,    g_gib);
    cudaGetSymbolAddress((void**)&ghb,    g_ghb);
    cudaGetSymbolAddress((void**)&sampb,  g_sampb);

    cudaFuncSetAttribute((const void*)tcb_gemm<128, 128, 64, 32>,
                         cudaFuncAttributeMaxDynamicSharedMemorySize, SMEM_BIG);
    cudaFuncSetAttribute((const void*)tcb_gemm<64, 128, 32, 32>,
                         cudaFuncAttributeMaxDynamicSharedMemorySize, SMEM_HALF);

    // launch 0: all fp32->bf16 conversions in one kernel
    conv_all_kernel<<<(F4_TOTAL + 255) / 256, 256>>>(
        x, (const float*)d_in[2], (const float*)d_in[4], (const float*)d_in[5],
        (const float*)d_in[8], (const float*)d_in[10],
        xb, Wab, Wihb, Whhb, Woutb, Wembb);
    // launch 1: e0
    init_e_kernel<<<(Bb * Ee + 255) / 256, 256>>>(eb, sos);

    GemmArgs Z = {};

    // launch 2: h0 = x @ W_agent^T + b_agent
    {
        GemmArgs a = {xb, Wab, b_agent, h, hb, DIN, Hh};
        tcb_gemm<64, 128, 32, 32><<<dim3(Hh / 128, Bb / 64, 1), 256, SMEM_HALF>>>(
            a, Z, DIN, DIN);
    }

    for (int l = 0; l < Ll; l++) {
        // gh (z=0, K=512) + gi (z=1, K=256) in one launch
        GemmArgs agh = {hb, Whhb, b_hh, nullptr, ghb, Hh, 3 * Hh};
        GemmArgs agi = {eb, Wihb, b_ih, nullptr, gib, Ee, 3 * Hh};
        tcb_gemm<128, 128, 64, 32><<<dim3(3 * Hh / 128, Bb / 128, 2), 256, SMEM_BIG>>>(
            agh, agi, Hh, Ee);
        // gates
        gru_gates_kernel<<<(Bb * Hh / 2 + 255) / 256, 256>>>(gib, ghb, h, hb);
        // logits = h @ W_out^T + b_out   <- ncu -s 5 -c 1 lands here (l=0)
        GemmArgs alo = {hb, Woutb, b_out, logits, nullptr, Hh, Vv};
        tcb_gemm<64, 128, 32, 32><<<dim3(Vv / 128, Bb / 64, 1), 256, SMEM_HALF>>>(
            alo, Z, Hh, Hh);
        // sample + entropy
        gumbel_softmax_kernel<<<Bb / 8, 256>>>(logits,
                                               noise + (size_t)l * Bb * Vv,
                                               seq + (size_t)l * Vv, sampb,
                                               ent + l);
        // e = sample @ W_emb^T + b_emb
        GemmArgs aem = {sampb, Wembb, b_emb, nullptr, eb, Vv, Ee};
        tcb_gemm<64, 128, 32, 32><<<dim3(Ee / 128, Bb / 64, 1), 256, SMEM_HALF>>>(
            aem, Z, Vv, Vv);
    }
    (void)in_sizes; (void)n_in; (void)out_size;
}

// round 12
// speedup vs baseline: 1.0582x; 1.0298x over previous
#include <cuda_runtime.h>
#include <cuda_bf16.h>
#include <math.h>
#include <stdint.h>

// Problem constants: B=4096, D_IN=512, H=512, E=256, V=512, L=32
#define Bb   4096
#define DIN  512
#define Hh   512
#define Ee   256
#define Vv   512
#define Ll   32
#define MIN_REAL_F (-3.4028234663852886e+38f)

// Persistent scratch (device globals; no allocations allowed)
__device__ float g_h[Bb * Hh];
__device__ float g_logits[Bb * Vv];

__device__ __nv_bfloat16 g_xb[Bb * DIN];
__device__ __nv_bfloat16 g_Wab[Hh * DIN];
__device__ __nv_bfloat16 g_Wihb[3 * Hh * Ee];
__device__ __nv_bfloat16 g_Whhb[3 * Hh * Hh];
__device__ __nv_bfloat16 g_Woutb[Vv * Hh];
__device__ __nv_bfloat16 g_Wembb[Ee * Vv];
__device__ __nv_bfloat16 g_hb[Bb * Hh];
__device__ __nv_bfloat16 g_eb[Bb * Ee];
__device__ __nv_bfloat16 g_gib[Bb * 3 * Hh];
__device__ __nv_bfloat16 g_ghb[Bb * 3 * Hh];
__device__ __nv_bfloat16 g_sampb[Bb * Vv];

// ---------------------------------------------------------------------------
// PTX helpers
// ---------------------------------------------------------------------------
__device__ __forceinline__ uint32_t smem_u32(const void* p) {
    return (uint32_t)__cvta_generic_to_shared(p);
}
__device__ __forceinline__ void cp16(uint32_t s, const void* g) {
    asm volatile("cp.async.cg.shared.global [%0], [%1], 16;\n" :: "r"(s), "l"(g));
}
__device__ __forceinline__ void cp_commit() {
    asm volatile("cp.async.commit_group;\n");
}
template<int N> __device__ __forceinline__ void cp_wait() {
    asm volatile("cp.async.wait_group %0;\n" :: "n"(N));
}
__device__ __forceinline__ void ldsm4(uint32_t& r0, uint32_t& r1,
                                      uint32_t& r2, uint32_t& r3, uint32_t a) {
    asm volatile("ldmatrix.sync.aligned.m8n8.x4.shared.b16 {%0,%1,%2,%3}, [%4];\n"
                 : "=r"(r0), "=r"(r1), "=r"(r2), "=r"(r3) : "r"(a));
}
__device__ __forceinline__ void mma_bf16(float c[4], const uint32_t a[4],
                                         uint32_t b0, uint32_t b1) {
    asm volatile(
        "mma.sync.aligned.m16n8k16.row.col.f32.bf16.bf16.f32 "
        "{%0,%1,%2,%3}, {%4,%5,%6,%7}, {%8,%9}, {%0,%1,%2,%3};\n"
        : "+f"(c[0]), "+f"(c[1]), "+f"(c[2]), "+f"(c[3])
        : "r"(a[0]), "r"(a[1]), "r"(a[2]), "r"(a[3]), "r"(b0), "r"(b1));
}

// ---------------------------------------------------------------------------
// bf16 HMMA GEMM:  out[M,N] = A[M,K] @ W[N,K]^T + bias
// BK=64 (128B rows), 3-stage cp.async, swizzle chunk c^(r&7).
// ldmatrix addressing uses the identity
//   ((kh*2+lsel)^(r&7))<<4 == (((lsel)^(r&7))<<4) ^ (kh<<5)
// so per-thread relative offsets are computed ONCE and per-kh addresses are a
// single XOR. Requires 128B-aligned smem stage bases.
// grid.z selects between two argument sets (fused independent GEMMs).
// ---------------------------------------------------------------------------
struct GemmArgs {
    const __nv_bfloat16* A;
    const __nv_bfloat16* W;
    const float* bias;
    float* C;                 // nullable fp32 out
    __nv_bfloat16* Cb;        // nullable bf16 out
    int lda;
    int ldc;
};

template<int BM, int BN, int WM, int WN>
__global__ __launch_bounds__(256) void tcb_gemm(GemmArgs a0, GemmArgs a1,
                                                int K0, int K1)
{
    constexpr int BK = 64;
    constexpr int STAGES = 3;
    constexpr int WARPS_M = BM / WM;
    constexpr int MI = WM / 16;
    constexpr int NJ = WN / 8;
    constexpr int NJ2 = WN / 16;
    constexpr int ACH = BM * 8 / 256;
    constexpr int WCH = BN * 8 / 256;
    constexpr int ABYTES = BM * 128;
    constexpr int WBYTES = BN * 128;

    extern __shared__ char dsm[];
    const GemmArgs ga = blockIdx.z ? a1 : a0;
    const int K = blockIdx.z ? K1 : K0;

    const uint32_t sbase = (smem_u32(dsm) + 127u) & ~127u;   // 128B aligned
    const uint32_t aBase = sbase;
    const uint32_t wBase = sbase + STAGES * ABYTES;

    const int tid  = threadIdx.x;
    const int warp = tid >> 5;
    const int lane = tid & 31;
    const int g = lane >> 2;
    const int t = lane & 3;
    const int wm = (warp % WARPS_M) * WM;
    const int wn = (warp / WARPS_M) * WN;
    const int bm = blockIdx.y * BM;
    const int bn = blockIdx.x * BN;
    const int lrow = lane & 15;
    const int lsel = lane >> 4;

    // per-thread relative ldmatrix offsets (swizzle folded in once)
    uint32_t aOff[MI], bOff[NJ2];
#pragma unroll
    for (int i = 0; i < MI; i++) {
        int row = wm + i * 16 + lrow;
        aOff[i] = row * 128 + ((lsel ^ (row & 7)) << 4);
    }
#pragma unroll
    for (int j = 0; j < NJ2; j++) {
        int row = wn + j * 16 + lrow;
        bOff[j] = row * 128 + ((lsel ^ (row & 7)) << 4);
    }

    float acc[MI][NJ][4];
#pragma unroll
    for (int i = 0; i < MI; i++)
#pragma unroll
        for (int j = 0; j < NJ; j++)
#pragma unroll
            for (int r = 0; r < 4; r++) acc[i][j][r] = 0.0f;

    const int T = K / BK;

    auto load_stage = [&](int s, int k0) {
        const __nv_bfloat16* Ap = ga.A + (size_t)bm * ga.lda + k0;
        const __nv_bfloat16* Wp = ga.W + (size_t)bn * K + k0;
        const uint32_t as = aBase + s * ABYTES;
        const uint32_t ws = wBase + s * WBYTES;
#pragma unroll
        for (int i = 0; i < ACH; i++) {
            int cid = tid + i * 256;
            int r = cid >> 3, c = cid & 7;
            cp16(as + r * 128 + ((c ^ (r & 7)) << 4),
                 Ap + (size_t)r * ga.lda + c * 8);
        }
#pragma unroll
        for (int i = 0; i < WCH; i++) {
            int cid = tid + i * 256;
            int r = cid >> 3, c = cid & 7;
            cp16(ws + r * 128 + ((c ^ (r & 7)) << 4),
                 Wp + (size_t)r * K + c * 8);
        }
    };

    load_stage(0, 0);  cp_commit();
    if (T > 1) load_stage(1, BK);
    cp_commit();

    for (int kt = 0; kt < T; kt++) {
        const int s = kt % STAGES;
        cp_wait<1>();
        __syncthreads();            // stage s ready; also guards reuse of s
        const int pf = kt + 2;
        if (pf < T) load_stage(pf % STAGES, pf * BK);
        cp_commit();

        const uint32_t as = aBase + s * ABYTES;
        const uint32_t ws = wBase + s * WBYTES;
        uint32_t aAbs[MI], bAbs[NJ2];
#pragma unroll
        for (int i = 0; i < MI; i++) aAbs[i] = as + aOff[i];
#pragma unroll
        for (int j = 0; j < NJ2; j++) bAbs[j] = ws + bOff[j];

#pragma unroll
        for (int kh = 0; kh < BK / 16; kh++) {
            const uint32_t kx = (uint32_t)kh << 5;
            uint32_t af[MI][4];
#pragma unroll
            for (int i = 0; i < MI; i++)
                ldsm4(af[i][0], af[i][1], af[i][2], af[i][3], aAbs[i] ^ kx);
            uint32_t bfr[NJ2][4];
#pragma unroll
            for (int j = 0; j < NJ2; j++)
                ldsm4(bfr[j][0], bfr[j][1], bfr[j][2], bfr[j][3], bAbs[j] ^ kx);
#pragma unroll
            for (int i = 0; i < MI; i++)
#pragma unroll
                for (int j = 0; j < NJ2; j++) {
                    mma_bf16(acc[i][2 * j],     af[i], bfr[j][0], bfr[j][2]);
                    mma_bf16(acc[i][2 * j + 1], af[i], bfr[j][1], bfr[j][3]);
                }
        }
        // no trailing sync: next iteration's top sync provides the ordering
    }

#pragma unroll
    for (int j = 0; j < NJ; j++) {
        const int col = bn + wn + j * 8 + 2 * t;
        const float b0 = ga.bias[col];
        const float b1 = ga.bias[col + 1];
#pragma unroll
        for (int i = 0; i < MI; i++) {
            const int row = bm + wm + i * 16 + g;
            float v00 = acc[i][j][0] + b0, v01 = acc[i][j][1] + b1;
            float v10 = acc[i][j][2] + b0, v11 = acc[i][j][3] + b1;
            if (ga.C) {
                *(float2*)(ga.C + (size_t)row * ga.ldc + col)       = make_float2(v00, v01);
                *(float2*)(ga.C + (size_t)(row + 8) * ga.ldc + col) = make_float2(v10, v11);
            }
            if (ga.Cb) {
                *(__nv_bfloat162*)(ga.Cb + (size_t)row * ga.ldc + col) =
                    __floats2bfloat162_rn(v00, v01);
                *(__nv_bfloat162*)(ga.Cb + (size_t)(row + 8) * ga.ldc + col) =
                    __floats2bfloat162_rn(v10, v11);
            }
        }
    }
}

// ---------------------------------------------------------------------------
// Fused fp32->bf16 conversion of all weights/inputs in ONE kernel.
// ---------------------------------------------------------------------------
#define F4_X    (Bb * DIN / 4)
#define F4_WA   (Hh * DIN / 4)
#define F4_WIH  (3 * Hh * Ee / 4)
#define F4_WHH  (3 * Hh * Hh / 4)
#define F4_WOUT (Vv * Hh / 4)
#define F4_WEMB (Ee * Vv / 4)
#define F4_TOTAL (F4_X + F4_WA + F4_WIH + F4_WHH + F4_WOUT + F4_WEMB)

__global__ void conv_all_kernel(
    const float* __restrict__ x,     const float* __restrict__ Wa,
    const float* __restrict__ Wih,   const float* __restrict__ Whh,
    const float* __restrict__ Wout,  const float* __restrict__ Wemb,
    __nv_bfloat16* __restrict__ xb,   __nv_bfloat16* __restrict__ Wab,
    __nv_bfloat16* __restrict__ Wihb, __nv_bfloat16* __restrict__ Whhb,
    __nv_bfloat16* __restrict__ Woutb, __nv_bfloat16* __restrict__ Wembb)
{
    int i = blockIdx.x * blockDim.x + threadIdx.x;
    if (i >= F4_TOTAL) return;
    const float* src; __nv_bfloat16* dst; int off = i;
    if (off < F4_X) { src = x; dst = xb; }
    else if ((off -= F4_X) < F4_WA) { src = Wa; dst = Wab; }
    else if ((off -= F4_WA) < F4_WIH) { src = Wih; dst = Wihb; }
    else if ((off -= F4_WIH) < F4_WHH) { src = Whh; dst = Whhb; }
    else if ((off -= F4_WHH) < F4_WOUT) { src = Wout; dst = Woutb; }
    else { off -= F4_WOUT; src = Wemb; dst = Wembb; }
    float4 v = ((const float4*)src)[off];
    ((__nv_bfloat162*)dst)[2 * off]     = __floats2bfloat162_rn(v.x, v.y);
    ((__nv_bfloat162*)dst)[2 * off + 1] = __floats2bfloat162_rn(v.z, v.w);
}

__global__ void init_e_kernel(__nv_bfloat16* __restrict__ eb,
                              const float* __restrict__ sos)
{
    int idx = blockIdx.x * blockDim.x + threadIdx.x;
    if (idx < Bb * Ee) eb[idx] = __float2bfloat16(sos[idx & (Ee - 1)]);
}

// ---------------------------------------------------------------------------
// GRU gates, 4 elements/thread (8B vector loads on gi/gh, 16B on h)
// ---------------------------------------------------------------------------
__device__ __forceinline__ float4 bf4_to_f4(uint2 u) {
    __nv_bfloat162 lo = *reinterpret_cast<__nv_bfloat162*>(&u.x);
    __nv_bfloat162 hi = *reinterpret_cast<__nv_bfloat162*>(&u.y);
    float2 a = __bfloat1622float2(lo), b = __bfloat1622float2(hi);
    return make_float4(a.x, a.y, b.x, b.y);
}

__global__ void gru_gates_kernel(const __nv_bfloat16* __restrict__ gi,
                                 const __nv_bfloat16* __restrict__ gh,
                                 float* __restrict__ h,
                                 __nv_bfloat16* __restrict__ hb)
{
    int idx = blockIdx.x * blockDim.x + threadIdx.x;
    if (idx >= Bb * Hh / 4) return;
    int b  = idx / (Hh / 4);
    int j4 = (idx - b * (Hh / 4)) * 4;

    const __nv_bfloat16* gib = gi + (size_t)b * 3 * Hh;
    const __nv_bfloat16* ghb = gh + (size_t)b * 3 * Hh;
    float4 ir  = bf4_to_f4(*(const uint2*)(gib + j4));
    float4 iz  = bf4_to_f4(*(const uint2*)(gib + Hh + j4));
    float4 inn = bf4_to_f4(*(const uint2*)(gib + 2 * Hh + j4));
    float4 hr  = bf4_to_f4(*(const uint2*)(ghb + j4));
    float4 hz  = bf4_to_f4(*(const uint2*)(ghb + Hh + j4));
    float4 hn  = bf4_to_f4(*(const uint2*)(ghb + 2 * Hh + j4));
    float4 hv  = *(float4*)(h + (size_t)b * Hh + j4);

    float4 o;
#define GATE(c) { \
        float r = 1.0f / (1.0f + expf(-(ir.c + hr.c))); \
        float z = 1.0f / (1.0f + expf(-(iz.c + hz.c))); \
        float n = tanhf(inn.c + r * hn.c); \
        o.c = (1.0f - z) * n + z * hv.c; }
    GATE(x) GATE(y) GATE(z) GATE(w)
#undef GATE
    *(float4*)(h + (size_t)b * Hh + j4) = o;
    __nv_bfloat162* hb2 = (__nv_bfloat162*)(hb + (size_t)b * Hh + j4);
    hb2[0] = __floats2bfloat162_rn(o.x, o.y);
    hb2[1] = __floats2bfloat162_rn(o.z, o.w);
}

// ---------------------------------------------------------------------------
// Gumbel-softmax + entropy, one WARP per row (V=512 -> 16 elems/lane)
// ---------------------------------------------------------------------------
__global__ __launch_bounds__(256) void gumbel_softmax_kernel(
    const float* __restrict__ logits,
    const float* __restrict__ noise,
    float* __restrict__ seq,
    __nv_bfloat16* __restrict__ sampb,
    float* __restrict__ ent)
{
    const int warp = threadIdx.x >> 5;
    const int lane = threadIdx.x & 31;
    const int b = blockIdx.x * 8 + warp;

    const float4* lg4 = (const float4*)(logits + (size_t)b * Vv);
    const float4* nz4 = (const float4*)(noise + (size_t)b * Vv);

    float tv[16];
    float m = -INFINITY;
#pragma unroll
    for (int i = 0; i < 4; i++) {
        float4 lv = lg4[i * 32 + lane];
        float4 uv = nz4[i * 32 + lane];
        tv[4 * i + 0] = lv.x - logf(-logf(uv.x));
        tv[4 * i + 1] = lv.y - logf(-logf(uv.y));
        tv[4 * i + 2] = lv.z - logf(-logf(uv.z));
        tv[4 * i + 3] = lv.w - logf(-logf(uv.w));
        m = fmaxf(m, fmaxf(fmaxf(tv[4 * i], tv[4 * i + 1]),
                           fmaxf(tv[4 * i + 2], tv[4 * i + 3])));
    }
#pragma unroll
    for (int o = 16; o; o >>= 1) m = fmaxf(m, __shfl_xor_sync(0xffffffffu, m, o));

    float s = 0.0f;
#pragma unroll
    for (int i = 0; i < 16; i++) { tv[i] = expf(tv[i] - m); s += tv[i]; }
#pragma unroll
    for (int o = 16; o; o >>= 1) s += __shfl_xor_sync(0xffffffffu, s, o);
    const float inv = 1.0f / s;

    float4* sq4 = (float4*)(seq + (size_t)b * (Ll * Vv));
    __nv_bfloat162* sb2 = (__nv_bfloat162*)(sampb + (size_t)b * Vv);
    float el = 0.0f;
#pragma unroll
    for (int i = 0; i < 4; i++) {
        float p0 = tv[4 * i] * inv,     p1 = tv[4 * i + 1] * inv;
        float p2 = tv[4 * i + 2] * inv, p3 = tv[4 * i + 3] * inv;
        sq4[i * 32 + lane] = make_float4(p0, p1, p2, p3);
        sb2[2 * (i * 32 + lane)]     = __floats2bfloat162_rn(p0, p1);
        sb2[2 * (i * 32 + lane) + 1] = __floats2bfloat162_rn(p2, p3);
        el += p0 * fmaxf(log2f(p0), MIN_REAL_F) + p1 * fmaxf(log2f(p1), MIN_REAL_F)
            + p2 * fmaxf(log2f(p2), MIN_REAL_F) + p3 * fmaxf(log2f(p3), MIN_REAL_F);
    }
#pragma unroll
    for (int o = 16; o; o >>= 1) el += __shfl_xor_sync(0xffffffffu, el, o);
    if (lane == 0) ent[(size_t)b * Ll] = -el;
}

// ---------------------------------------------------------------------------
// Host launcher (single stream)
// ---------------------------------------------------------------------------
#define SMEM_BIG  ((3 * (128 + 128) * 128) + 128)   // 98432
#define SMEM_HALF ((3 * (64 + 128) * 128) + 128)    // 73856
#define SMEM_QTR  ((3 * (64 + 64) * 128) + 128)     // 49280

extern "C" void kernel_launch(void* const* d_in, const int* in_sizes, int n_in,
                              void* d_out, int out_size)
{
    const float* x       = (const float*)d_in[0];
    const float* noise   = (const float*)d_in[1];
    const float* b_agent = (const float*)d_in[3];
    const float* b_ih    = (const float*)d_in[6];
    const float* b_hh    = (const float*)d_in[7];
    const float* b_out   = (const float*)d_in[9];
    const float* b_emb   = (const float*)d_in[11];
    const float* sos     = (const float*)d_in[12];

    float* out = (float*)d_out;
    float* seq = out;                              // [B,L,V]
    float* ent = out + (size_t)Bb * Ll * Vv;       // [B,L]

    float *h, *logits;
    __nv_bfloat16 *xb, *Wab, *Wihb, *Whhb, *Woutb, *Wembb;
    __nv_bfloat16 *hb, *eb, *gib, *ghb, *sampb;
    cudaGetSymbolAddress((void**)&h,      g_h);
    cudaGetSymbolAddress((void**)&logits, g_logits);
    cudaGetSymbolAddress((void**)&xb,     g_xb);
    cudaGetSymbolAddress((void**)&Wab,    g_Wab);
    cudaGetSymbolAddress((void**)&Wihb,   g_Wihb);
    cudaGetSymbolAddress((void**)&Whhb,   g_Whhb);
    cudaGetSymbolAddress((void**)&Woutb,  g_Woutb);
    cudaGetSymbolAddress((void**)&Wembb,  g_Wembb);
    cudaGetSymbolAddress((void**)&hb,     g_hb);
    cudaGetSymbolAddress((void**)&eb,     g_eb);
    cudaGetSymbolAddress((void**)&gib,    g_gib);
    cudaGetSymbolAddress((void**)&ghb,    g_ghb);
    cudaGetSymbolAddress((void**)&sampb,  g_sampb);

    cudaFuncSetAttribute((const void*)tcb_gemm<128, 128, 64, 32>,
                         cudaFuncAttributeMaxDynamicSharedMemorySize, SMEM_BIG);
    cudaFuncSetAttribute((const void*)tcb_gemm<64, 128, 32, 32>,
                         cudaFuncAttributeMaxDynamicSharedMemorySize, SMEM_HALF);
    cudaFuncSetAttribute((const void*)tcb_gemm<64, 64, 32, 16>,
                         cudaFuncAttributeMaxDynamicSharedMemorySize, SMEM_QTR);

    // launch 0: all fp32->bf16 conversions in one kernel
    conv_all_kernel<<<(F4_TOTAL + 255) / 256, 256>>>(
        x, (const float*)d_in[2], (const float*)d_in[4], (const float*)d_in[5],
        (const float*)d_in[8], (const float*)d_in[10],
        xb, Wab, Wihb, Whhb, Woutb, Wembb);
    // launch 1: e0
    init_e_kernel<<<(Bb * Ee + 255) / 256, 256>>>(eb, sos);

    GemmArgs Z = {};

    // launch 2: h0 = x @ W_agent^T + b_agent
    {
        GemmArgs a = {xb, Wab, b_agent, h, hb, DIN, Hh};
        tcb_gemm<64, 128, 32, 32><<<dim3(Hh / 128, Bb / 64, 1), 256, SMEM_HALF>>>(
            a, Z, DIN, DIN);
    }

    for (int l = 0; l < Ll; l++) {
        // gh (z=0, K=512) + gi (z=1, K=256) in one launch
        GemmArgs agh = {hb, Whhb, b_hh, nullptr, ghb, Hh, 3 * Hh};
        GemmArgs agi = {eb, Wihb, b_ih, nullptr, gib, Ee, 3 * Hh};
        tcb_gemm<128, 128, 64, 32><<<dim3(3 * Hh / 128, Bb / 128, 2), 256, SMEM_BIG>>>(
            agh, agi, Hh, Ee);
        // gates
        gru_gates_kernel<<<(Bb * Hh / 4 + 255) / 256, 256>>>(gib, ghb, h, hb);
        // logits = h @ W_out^T + b_out
        GemmArgs alo = {hb, Woutb, b_out, logits, nullptr, Hh, Vv};
        tcb_gemm<64, 128, 32, 32><<<dim3(Vv / 128, Bb / 64, 1), 256, SMEM_HALF>>>(
            alo, Z, Hh, Hh);
        // sample + entropy
        gumbel_softmax_kernel<<<Bb / 8, 256>>>(logits,
                                               noise + (size_t)l * Bb * Vv,
                                               seq + (size_t)l * Vv, sampb,
                                               ent + l);
        // e = sample @ W_emb^T + b_emb  (64x64 tiles -> 256 CTAs, full wave)
        GemmArgs aem = {sampb, Wembb, b_emb, nullptr, eb, Vv, Ee};
        tcb_gemm<64, 64, 32, 16><<<dim3(Ee / 64, Bb / 64, 1), 256, SMEM_QTR>>>(
            aem, Z, Vv, Vv);
    }
    (void)in_sizes; (void)n_in; (void)out_size;
}